// round 2
// baseline (speedup 1.0000x reference)
#include <cuda_runtime.h>
#include <cuda_bf16.h>
#include <cstdint>

// ContactMapHead:
//   h = relu(hidden[4,2048,1024] @ proj_w[256,1024]^T + proj_b)   -> bf16 scratch
//   out[b] = (h[b] @ h[b]^T) * clf_w + clf_b                      -> [4,2048,2048] fp32
//
// Both GEMMs are C = A[M,K] * B[N,K]^T with K-contiguous operands, so one
// mma.sync bf16 kernel serves both. 128x128x64 block tile, 8 warps (2x4),
// 64x32 warp tile, SW128 smem swizzle, double-buffered smem + reg prefetch.

#define BM 128
#define BN 128
#define BK 64
#define NTHREADS 256

// 4 * 2048 * 256 bf16 = 4 Mi elems (8 MB) scratch for h
__device__ __nv_bfloat16 g_h[4 * 2048 * 256];

static __device__ __forceinline__ uint32_t smem_u32(const void* p) {
    return (uint32_t)__cvta_generic_to_shared(p);
}

static __device__ __forceinline__ void ldsm_x4(unsigned r[4], uint32_t a) {
    asm volatile("ldmatrix.sync.aligned.m8n8.x4.shared.b16 {%0,%1,%2,%3}, [%4];"
                 : "=r"(r[0]), "=r"(r[1]), "=r"(r[2]), "=r"(r[3]) : "r"(a));
}
static __device__ __forceinline__ void ldsm_x2(unsigned r[2], uint32_t a) {
    asm volatile("ldmatrix.sync.aligned.m8n8.x2.shared.b16 {%0,%1}, [%2];"
                 : "=r"(r[0]), "=r"(r[1]) : "r"(a));
}
static __device__ __forceinline__ void mma16816(float c[4], const unsigned a[4], const unsigned b[2]) {
    asm volatile("mma.sync.aligned.m16n8k16.row.col.f32.bf16.bf16.f32 "
                 "{%0,%1,%2,%3}, {%4,%5,%6,%7}, {%8,%9}, {%0,%1,%2,%3};"
                 : "+f"(c[0]), "+f"(c[1]), "+f"(c[2]), "+f"(c[3])
                 : "r"(a[0]), "r"(a[1]), "r"(a[2]), "r"(a[3]), "r"(b[0]), "r"(b[1]));
}

static __device__ __forceinline__ unsigned packbf(float a, float b) {
    __nv_bfloat162 t = __floats2bfloat162_rn(a, b);
    return *reinterpret_cast<unsigned*>(&t);
}

// Per-thread tile fragment: 4 chunks of 8 elements (tile = 128 rows x 64 cols,
// 8 chunks/row, 1024 chunks, 256 threads -> 4 chunks/thread).
struct RegsF { float4 v[8]; };  // fp32 source: 2 float4 per chunk
struct RegsH { uint4 v[4]; };   // bf16 source: 1 uint4 per chunk

static __device__ __forceinline__ void ldg_tile(RegsF& r, const float* base, int rowBase,
                                                int kBase, int ld, int tid) {
#pragma unroll
    for (int i = 0; i < 4; i++) {
        int c = tid + i * NTHREADS;
        int row = c >> 3, ch = c & 7;
        const float4* p = (const float4*)(base + (size_t)(rowBase + row) * ld + kBase + ch * 8);
        r.v[2 * i] = p[0];
        r.v[2 * i + 1] = p[1];
    }
}
static __device__ __forceinline__ void ldg_tile(RegsH& r, const __nv_bfloat16* base, int rowBase,
                                                int kBase, int ld, int tid) {
#pragma unroll
    for (int i = 0; i < 4; i++) {
        int c = tid + i * NTHREADS;
        int row = c >> 3, ch = c & 7;
        r.v[i] = *(const uint4*)(base + (size_t)(rowBase + row) * ld + kBase + ch * 8);
    }
}
// SW128 swizzle: 128B rows (64 bf16), 16B chunk index XOR (row & 7).
static __device__ __forceinline__ void sts_tile(const RegsF& r, char* s, int tid) {
#pragma unroll
    for (int i = 0; i < 4; i++) {
        int c = tid + i * NTHREADS;
        int row = c >> 3, ch = c & 7;
        uint4 v;
        v.x = packbf(r.v[2 * i].x, r.v[2 * i].y);
        v.y = packbf(r.v[2 * i].z, r.v[2 * i].w);
        v.z = packbf(r.v[2 * i + 1].x, r.v[2 * i + 1].y);
        v.w = packbf(r.v[2 * i + 1].z, r.v[2 * i + 1].w);
        *(uint4*)(s + row * 128 + ((ch ^ (row & 7)) << 4)) = v;
    }
}
static __device__ __forceinline__ void sts_tile(const RegsH& r, char* s, int tid) {
#pragma unroll
    for (int i = 0; i < 4; i++) {
        int c = tid + i * NTHREADS;
        int row = c >> 3, ch = c & 7;
        *(uint4*)(s + row * 128 + ((ch ^ (row & 7)) << 4)) = r.v[i];
    }
}

template <bool RELU>
struct Cfg;
template <>
struct Cfg<true> { using InT = float; using Regs = RegsF; };   // GEMM1: fp32 in, bf16 h out
template <>
struct Cfg<false> { using InT = __nv_bfloat16; using Regs = RegsH; };  // GEMM2: bf16 in, fp32 out

template <bool RELU>
__global__ __launch_bounds__(NTHREADS, 1) void gemm_kernel(
    const typename Cfg<RELU>::InT* __restrict__ Ain,
    const typename Cfg<RELU>::InT* __restrict__ Bin,
    const float* __restrict__ bias,
    const float* __restrict__ clfw, const float* __restrict__ clfb,
    float* __restrict__ outF,
    int K, int ldo, long sA, long sB, long sO) {
    using InT = typename Cfg<RELU>::InT;
    using Regs = typename Cfg<RELU>::Regs;

    extern __shared__ __align__(16) char smem[];
    const int tid = threadIdx.x;
    const int warp = tid >> 5, lane = tid & 31;
    const int wm = (warp >> 2) * 64;  // warp row offset (2 warps along M)
    const int wn = (warp & 3) * 32;   // warp col offset (4 warps along N)
    const long bz = blockIdx.z;

    const InT* Ab;
    const InT* Bb;
    if (RELU) {
        Ab = Ain;  // hidden, treated as [8192,1024]
        Bb = Bin;  // proj_w [256,1024]
    } else {
        Ab = (const InT*)(g_h) + bz * sA;
        Bb = (const InT*)(g_h) + bz * sB;
    }
    const int mBase = blockIdx.y * BM;
    const int nBase = blockIdx.x * BN;

    float acc[4][4][4];
#pragma unroll
    for (int mi = 0; mi < 4; mi++)
#pragma unroll
        for (int ni = 0; ni < 4; ni++)
#pragma unroll
            for (int j = 0; j < 4; j++) acc[mi][ni][j] = 0.f;

    const int nk = K / BK;
    Regs rA, rB;
    ldg_tile(rA, Ab, mBase, 0, K, tid);
    ldg_tile(rB, Bb, nBase, 0, K, tid);
    sts_tile(rA, smem, tid);
    sts_tile(rB, smem + 16384, tid);
    __syncthreads();

    for (int kt = 0; kt < nk; kt++) {
        if (kt + 1 < nk) {
            ldg_tile(rA, Ab, mBase, (kt + 1) * BK, K, tid);
            ldg_tile(rB, Bb, nBase, (kt + 1) * BK, K, tid);
        }
        char* sa = smem + (kt & 1) * 32768;
        uint32_t aB = smem_u32(sa);
        uint32_t bB = aB + 16384;
#pragma unroll
        for (int ks = 0; ks < 4; ks++) {
            unsigned af[4][4], bfr[4][2];
#pragma unroll
            for (int mi = 0; mi < 4; mi++) {
                int row = wm + mi * 16 + (lane & 15);
                int kch = ks * 2 + (lane >> 4);
                ldsm_x4(af[mi], aB + row * 128 + ((kch ^ (row & 7)) << 4));
            }
#pragma unroll
            for (int ni = 0; ni < 4; ni++) {
                int nr = wn + ni * 8 + (lane & 7);
                int kch = ks * 2 + ((lane >> 3) & 1);
                ldsm_x2(bfr[ni], bB + nr * 128 + ((kch ^ (nr & 7)) << 4));
            }
#pragma unroll
            for (int mi = 0; mi < 4; mi++)
#pragma unroll
                for (int ni = 0; ni < 4; ni++) mma16816(acc[mi][ni], af[mi], bfr[ni]);
        }
        if (kt + 1 < nk) {
            char* da = smem + ((kt + 1) & 1) * 32768;
            sts_tile(rA, da, tid);
            sts_tile(rB, da + 16384, tid);
            __syncthreads();
        }
    }

    // Epilogue. c0,c1 -> (row, col..col+1); c2,c3 -> (row+8, col..col+1)
    if (RELU) {
#pragma unroll
        for (int mi = 0; mi < 4; mi++) {
            int r = mBase + wm + mi * 16 + (lane >> 2);
#pragma unroll
            for (int ni = 0; ni < 4; ni++) {
                int cidx = nBase + wn + ni * 8 + ((lane & 3) << 1);
                float b0 = bias[cidx], b1 = bias[cidx + 1];
                float v00 = fmaxf(acc[mi][ni][0] + b0, 0.f);
                float v01 = fmaxf(acc[mi][ni][1] + b1, 0.f);
                float v10 = fmaxf(acc[mi][ni][2] + b0, 0.f);
                float v11 = fmaxf(acc[mi][ni][3] + b1, 0.f);
                __nv_bfloat162 h0 = __floats2bfloat162_rn(v00, v01);
                __nv_bfloat162 h1 = __floats2bfloat162_rn(v10, v11);
                *(__nv_bfloat162*)&g_h[(size_t)r * ldo + cidx] = h0;
                *(__nv_bfloat162*)&g_h[(size_t)(r + 8) * ldo + cidx] = h1;
            }
        }
    } else {
        float w = clfw[0], bb = clfb[0];
        float* op = outF + bz * sO;
#pragma unroll
        for (int mi = 0; mi < 4; mi++) {
            int r = mBase + wm + mi * 16 + (lane >> 2);
#pragma unroll
            for (int ni = 0; ni < 4; ni++) {
                int cidx = nBase + wn + ni * 8 + ((lane & 3) << 1);
                float2 v0 = make_float2(fmaf(acc[mi][ni][0], w, bb), fmaf(acc[mi][ni][1], w, bb));
                float2 v1 = make_float2(fmaf(acc[mi][ni][2], w, bb), fmaf(acc[mi][ni][3], w, bb));
                *(float2*)&op[(size_t)r * ldo + cidx] = v0;
                *(float2*)&op[(size_t)(r + 8) * ldo + cidx] = v1;
            }
        }
    }
}

extern "C" void kernel_launch(void* const* d_in, const int* in_sizes, int n_in,
                              void* d_out, int out_size) {
    (void)in_sizes; (void)n_in; (void)out_size;
    const float* hidden = (const float*)d_in[0];   // [4,2048,1024]
    const float* proj_w = (const float*)d_in[1];   // [256,1024]
    const float* proj_b = (const float*)d_in[2];   // [256]
    const float* clf_w  = (const float*)d_in[3];   // [1,1]
    const float* clf_b  = (const float*)d_in[4];   // [1]
    float* out = (float*)d_out;                    // [4,2048,2048]

    cudaFuncSetAttribute(gemm_kernel<true>, cudaFuncAttributeMaxDynamicSharedMemorySize, 65536);
    cudaFuncSetAttribute(gemm_kernel<false>, cudaFuncAttributeMaxDynamicSharedMemorySize, 65536);

    // GEMM1: [8192,1024] x [256,1024]^T -> relu -> g_h (bf16, ld 256)
    dim3 g1(256 / BN, 8192 / BM, 1);
    gemm_kernel<true><<<g1, NTHREADS, 65536>>>(
        hidden, proj_w, proj_b, nullptr, nullptr, nullptr,
        1024, 256, 0, 0, 0);

    // GEMM2: per batch, [2048,256] x [2048,256]^T * clf_w + clf_b -> out (fp32, ld 2048)
    dim3 g2(2048 / BN, 2048 / BM, 4);
    gemm_kernel<false><<<g2, NTHREADS, 65536>>>(
        nullptr, nullptr, nullptr, clf_w, clf_b, out,
        256, 2048, 2048L * 256, 2048L * 256, 2048L * 2048);
}

// round 5
// speedup vs baseline: 1.3284x; 1.3284x over previous
#include <cuda_runtime.h>
#include <cuda_bf16.h>
#include <cstdint>

// ContactMapHead, mma.sync path (tcgen05 unavailable: harness targets compute_103,
// arch-specific 'a' features rejected by ptxas).
//   GEMM1 (proj_mma): h = relu(hidden @ W^T + b) -> g_h bf16 [8192,256]  (R2-proven code)
//   GEMM2 (gram_mma): out[b] = (h[b] h[b]^T)*w + c, SYMMETRIC -> triangle tiles only,
//                     cp.async double-buffered, 2 CTAs/SM, mirrored tile via smem transpose.

__device__ __nv_bfloat16 g_h[4 * 2048 * 256];

static __device__ __forceinline__ uint32_t smem_u32(const void* p) {
    return (uint32_t)__cvta_generic_to_shared(p);
}
static __device__ __forceinline__ void ldsm_x4(unsigned r[4], uint32_t a) {
    asm volatile("ldmatrix.sync.aligned.m8n8.x4.shared.b16 {%0,%1,%2,%3}, [%4];"
                 : "=r"(r[0]), "=r"(r[1]), "=r"(r[2]), "=r"(r[3]) : "r"(a));
}
static __device__ __forceinline__ void ldsm_x2(unsigned r[2], uint32_t a) {
    asm volatile("ldmatrix.sync.aligned.m8n8.x2.shared.b16 {%0,%1}, [%2];"
                 : "=r"(r[0]), "=r"(r[1]) : "r"(a));
}
static __device__ __forceinline__ void mma16816(float c[4], const unsigned a[4], const unsigned b[2]) {
    asm volatile("mma.sync.aligned.m16n8k16.row.col.f32.bf16.bf16.f32 "
                 "{%0,%1,%2,%3}, {%4,%5,%6,%7}, {%8,%9}, {%0,%1,%2,%3};"
                 : "+f"(c[0]), "+f"(c[1]), "+f"(c[2]), "+f"(c[3])
                 : "r"(a[0]), "r"(a[1]), "r"(a[2]), "r"(a[3]), "r"(b[0]), "r"(b[1]));
}
static __device__ __forceinline__ unsigned packbf(float a, float b) {
    __nv_bfloat162 t = __floats2bfloat162_rn(a, b);
    return *reinterpret_cast<unsigned*>(&t);
}
static __device__ __forceinline__ void cp16(uint32_t saddr, const void* gptr) {
    asm volatile("cp.async.cg.shared.global [%0], [%1], 16;" :: "r"(saddr), "l"(gptr) : "memory");
}
static __device__ __forceinline__ void cp_commit() {
    asm volatile("cp.async.commit_group;" ::: "memory");
}
static __device__ __forceinline__ void cp_wait1() {
    asm volatile("cp.async.wait_group 1;" ::: "memory");
}
static __device__ __forceinline__ void cp_wait0() {
    asm volatile("cp.async.wait_group 0;" ::: "memory");
}

// =====================================================================
// GEMM1 (unchanged from R2's passing kernel): 128x128 tile, BK=64 double
// buffer, fp32->bf16 convert on STS path, bias+relu epilogue -> g_h.
// =====================================================================
#define NT 256

struct RegsF { float4 v[8]; };

static __device__ __forceinline__ void ldg_tileF(RegsF& r, const float* base, int rowBase,
                                                 int kBase, int ld, int tid) {
#pragma unroll
    for (int i = 0; i < 4; i++) {
        int c = tid + i * NT;
        int row = c >> 3, ch = c & 7;
        const float4* p = (const float4*)(base + (size_t)(rowBase + row) * ld + kBase + ch * 8);
        r.v[2 * i] = p[0];
        r.v[2 * i + 1] = p[1];
    }
}
static __device__ __forceinline__ void sts_tileF(const RegsF& r, char* s, int tid) {
#pragma unroll
    for (int i = 0; i < 4; i++) {
        int c = tid + i * NT;
        int row = c >> 3, ch = c & 7;
        uint4 v;
        v.x = packbf(r.v[2 * i].x, r.v[2 * i].y);
        v.y = packbf(r.v[2 * i].z, r.v[2 * i].w);
        v.z = packbf(r.v[2 * i + 1].x, r.v[2 * i + 1].y);
        v.w = packbf(r.v[2 * i + 1].z, r.v[2 * i + 1].w);
        *(uint4*)(s + row * 128 + ((ch ^ (row & 7)) << 4)) = v;
    }
}

__global__ __launch_bounds__(NT, 1) void proj_mma(const float* __restrict__ Ain,
                                                  const float* __restrict__ Bin,
                                                  const float* __restrict__ bias) {
    extern __shared__ __align__(16) char smem[];
    const int tid = threadIdx.x;
    const int warp = tid >> 5, lane = tid & 31;
    const int wm = (warp >> 2) * 64;
    const int wn = (warp & 3) * 32;
    const int mBase = blockIdx.y * 128;
    const int nBase = blockIdx.x * 128;
    const int K = 1024;

    float acc[4][4][4];
#pragma unroll
    for (int mi = 0; mi < 4; mi++)
#pragma unroll
        for (int ni = 0; ni < 4; ni++)
#pragma unroll
            for (int j = 0; j < 4; j++) acc[mi][ni][j] = 0.f;

    const int nk = K / 64;
    RegsF rA, rB;
    ldg_tileF(rA, Ain, mBase, 0, K, tid);
    ldg_tileF(rB, Bin, nBase, 0, K, tid);
    sts_tileF(rA, smem, tid);
    sts_tileF(rB, smem + 16384, tid);
    __syncthreads();

    for (int kt = 0; kt < nk; kt++) {
        if (kt + 1 < nk) {
            ldg_tileF(rA, Ain, mBase, (kt + 1) * 64, K, tid);
            ldg_tileF(rB, Bin, nBase, (kt + 1) * 64, K, tid);
        }
        char* sa = smem + (kt & 1) * 32768;
        uint32_t aB = smem_u32(sa);
        uint32_t bB = aB + 16384;
#pragma unroll
        for (int ks = 0; ks < 4; ks++) {
            unsigned af[4][4], bfr[4][2];
#pragma unroll
            for (int mi = 0; mi < 4; mi++) {
                int row = wm + mi * 16 + (lane & 15);
                int kch = ks * 2 + (lane >> 4);
                ldsm_x4(af[mi], aB + row * 128 + ((kch ^ (row & 7)) << 4));
            }
#pragma unroll
            for (int ni = 0; ni < 4; ni++) {
                int nr = wn + ni * 8 + (lane & 7);
                int kch = ks * 2 + ((lane >> 3) & 1);
                ldsm_x2(bfr[ni], bB + nr * 128 + ((kch ^ (nr & 7)) << 4));
            }
#pragma unroll
            for (int mi = 0; mi < 4; mi++)
#pragma unroll
                for (int ni = 0; ni < 4; ni++) mma16816(acc[mi][ni], af[mi], bfr[ni]);
        }
        if (kt + 1 < nk) {
            char* da = smem + ((kt + 1) & 1) * 32768;
            sts_tileF(rA, da, tid);
            sts_tileF(rB, da + 16384, tid);
            __syncthreads();
        }
    }

#pragma unroll
    for (int mi = 0; mi < 4; mi++) {
        int r = mBase + wm + mi * 16 + (lane >> 2);
#pragma unroll
        for (int ni = 0; ni < 4; ni++) {
            int cidx = nBase + wn + ni * 8 + ((lane & 3) << 1);
            float b0 = bias[cidx], b1 = bias[cidx + 1];
            float v00 = fmaxf(acc[mi][ni][0] + b0, 0.f);
            float v01 = fmaxf(acc[mi][ni][1] + b1, 0.f);
            float v10 = fmaxf(acc[mi][ni][2] + b0, 0.f);
            float v11 = fmaxf(acc[mi][ni][3] + b1, 0.f);
            __nv_bfloat162 h0 = __floats2bfloat162_rn(v00, v01);
            __nv_bfloat162 h1 = __floats2bfloat162_rn(v10, v11);
            *(__nv_bfloat162*)&g_h[(size_t)r * 256 + cidx] = h0;
            *(__nv_bfloat162*)&g_h[(size_t)(r + 8) * 256 + cidx] = h1;
        }
    }
}

// =====================================================================
// GEMM2: triangle tiles of the symmetric Gram matrix.
// CTA tile 128x128, K=256 in 4 chunks of 64, cp.async 2-stage pipeline,
// 2 CTAs/SM. Tile (i,j), i<=j; off-diagonal mirror written via smem
// transpose staging (stride 132 floats, conflict-free).
// SMEM union: pipeline buf s: A @ s*32768 (16KB), B @ s*32768+16384 (16KB)
//             then reused as Ct staging 128x132 fp32 (67584 B total smem).
// =====================================================================
__global__ __launch_bounds__(NT, 2) void gram_mma(const float* __restrict__ clfw,
                                                  const float* __restrict__ clfb,
                                                  float* __restrict__ out) {
    extern __shared__ __align__(16) char smem[];
    const uint32_t sb = smem_u32(smem);
    const int tid = threadIdx.x;
    const int warp = tid >> 5, lane = tid & 31;
    const int wm = (warp >> 2) * 64;
    const int wn = (warp & 3) * 32;
    const int b = blockIdx.y;

    // triangular index -> (i, j), i <= j, 16 M/N tiles
    int t = blockIdx.x, ti = 0;
    while (t >= 16 - ti) { t -= 16 - ti; ti++; }
    const int tj = ti + t;
    const int mBase = ti * 128, nBase = tj * 128;
    const __nv_bfloat16* hb = g_h + (size_t)b * (2048 * 256);

    // issue chunk kt into buffer buf
    auto issue = [&](int kt, int buf) {
        const uint32_t A0 = sb + buf * 32768, B0 = A0 + 16384;
#pragma unroll
        for (int i = 0; i < 4; i++) {
            int c = tid + i * NT;          // 1024 chunks: 128 rows x 8
            int r = c >> 3, ch = c & 7;
            uint32_t dst = (uint32_t)(r * 128 + ((ch ^ (r & 7)) << 4));
            cp16(A0 + dst, hb + (size_t)(mBase + r) * 256 + kt * 64 + ch * 8);
            cp16(B0 + dst, hb + (size_t)(nBase + r) * 256 + kt * 64 + ch * 8);
        }
        cp_commit();
    };

    float acc[4][4][4];
#pragma unroll
    for (int mi = 0; mi < 4; mi++)
#pragma unroll
        for (int ni = 0; ni < 4; ni++)
#pragma unroll
            for (int j = 0; j < 4; j++) acc[mi][ni][j] = 0.f;

    issue(0, 0);
    issue(1, 1);

    for (int kt = 0; kt < 4; kt++) {
        if (kt < 3) cp_wait1(); else cp_wait0();
        __syncthreads();
        const uint32_t aB = sb + (kt & 1) * 32768, bB = aB + 16384;
#pragma unroll
        for (int ks = 0; ks < 4; ks++) {
            unsigned af[4][4], bfr[4][2];
#pragma unroll
            for (int mi = 0; mi < 4; mi++) {
                int row = wm + mi * 16 + (lane & 15);
                int kch = ks * 2 + (lane >> 4);
                ldsm_x4(af[mi], aB + row * 128 + ((kch ^ (row & 7)) << 4));
            }
#pragma unroll
            for (int ni = 0; ni < 4; ni++) {
                int nr = wn + ni * 8 + (lane & 7);
                int kch = ks * 2 + ((lane >> 3) & 1);
                ldsm_x2(bfr[ni], bB + nr * 128 + ((kch ^ (nr & 7)) << 4));
            }
#pragma unroll
            for (int mi = 0; mi < 4; mi++)
#pragma unroll
                for (int ni = 0; ni < 4; ni++) mma16816(acc[mi][ni], af[mi], bfr[ni]);
        }
        __syncthreads();
        if (kt + 2 < 4) issue(kt + 2, kt & 1);
    }

    const float w = clfw[0], cb = clfb[0];
    float* op = out + (size_t)b * 2048 * 2048;
    float* ct = (float*)smem;  // 128 x 132 staging (transposed tile)

    // direct write of tile (i,j) + stage transpose
#pragma unroll
    for (int mi = 0; mi < 4; mi++) {
        int lr = wm + mi * 16 + (lane >> 2);
#pragma unroll
        for (int ni = 0; ni < 4; ni++) {
            int lc = wn + ni * 8 + ((lane & 3) << 1);
            float v00 = fmaf(acc[mi][ni][0], w, cb);
            float v01 = fmaf(acc[mi][ni][1], w, cb);
            float v10 = fmaf(acc[mi][ni][2], w, cb);
            float v11 = fmaf(acc[mi][ni][3], w, cb);
            *(float2*)&op[(size_t)(mBase + lr) * 2048 + nBase + lc] = make_float2(v00, v01);
            *(float2*)&op[(size_t)(mBase + lr + 8) * 2048 + nBase + lc] = make_float2(v10, v11);
            if (ti != tj) {
                ct[lc * 132 + lr] = v00;
                ct[(lc + 1) * 132 + lr] = v01;
                ct[lc * 132 + lr + 8] = v10;
                ct[(lc + 1) * 132 + lr + 8] = v11;
            }
        }
    }
    if (ti != tj) {
        __syncthreads();
        // coalesced write of mirrored tile out[nBase+rr][mBase+..]
#pragma unroll
        for (int idx = tid; idx < 4096; idx += NT) {
            int rr = idx >> 5, cc = idx & 31;
            float4 v = *(float4*)&ct[rr * 132 + cc * 4];
            *(float4*)&op[(size_t)(nBase + rr) * 2048 + mBase + cc * 4] = v;
        }
    }
}

extern "C" void kernel_launch(void* const* d_in, const int* in_sizes, int n_in,
                              void* d_out, int out_size) {
    (void)in_sizes; (void)n_in; (void)out_size;
    const float* hidden = (const float*)d_in[0];  // [4,2048,1024]
    const float* proj_w = (const float*)d_in[1];  // [256,1024]
    const float* proj_b = (const float*)d_in[2];  // [256]
    const float* clf_w = (const float*)d_in[3];   // [1,1]
    const float* clf_b = (const float*)d_in[4];   // [1]
    float* out = (float*)d_out;                   // [4,2048,2048]

    cudaFuncSetAttribute(proj_mma, cudaFuncAttributeMaxDynamicSharedMemorySize, 65536);
    cudaFuncSetAttribute(gram_mma, cudaFuncAttributeMaxDynamicSharedMemorySize, 67584);

    // GEMM1: [8192,1024] x [256,1024]^T -> relu -> g_h
    proj_mma<<<dim3(2, 64), NT, 65536>>>(hidden, proj_w, proj_b);
    // GEMM2: 136 triangle tiles x 4 batches
    gram_mma<<<dim3(136, 4), NT, 67584>>>(clf_w, clf_b, out);
}

// round 6
// speedup vs baseline: 1.3901x; 1.0464x over previous
#include <cuda_runtime.h>
#include <cuda_bf16.h>
#include <cstdint>

// ContactMapHead, mma.sync path (tcgen05 rejected: harness targets compute_103).
//   cvt_w:    proj_w fp32 -> g_w bf16 (once)
//   proj_mma: h = relu(hidden @ W^T + b) -> g_h bf16 [8192,256]
//             tile 64x128, 256 CTAs, occ 2, A: LDG->cvt->STS, B: cp.async bf16,
//             ONE sync per kt.
//   gram_mma: out[b] = (h[b] h[b]^T)*w + c, triangle tiles, 3-stage cp.async,
//             ONE sync per kt, mirror via smem transpose.

__device__ __nv_bfloat16 g_h[4 * 2048 * 256];
__device__ __nv_bfloat16 g_w[256 * 1024];

static __device__ __forceinline__ uint32_t smem_u32(const void* p) {
    return (uint32_t)__cvta_generic_to_shared(p);
}
static __device__ __forceinline__ void ldsm_x4(unsigned r[4], uint32_t a) {
    asm volatile("ldmatrix.sync.aligned.m8n8.x4.shared.b16 {%0,%1,%2,%3}, [%4];"
                 : "=r"(r[0]), "=r"(r[1]), "=r"(r[2]), "=r"(r[3]) : "r"(a));
}
static __device__ __forceinline__ void mma16816(float c[4], const unsigned a[4], const unsigned b[2]) {
    asm volatile("mma.sync.aligned.m16n8k16.row.col.f32.bf16.bf16.f32 "
                 "{%0,%1,%2,%3}, {%4,%5,%6,%7}, {%8,%9}, {%0,%1,%2,%3};"
                 : "+f"(c[0]), "+f"(c[1]), "+f"(c[2]), "+f"(c[3])
                 : "r"(a[0]), "r"(a[1]), "r"(a[2]), "r"(a[3]), "r"(b[0]), "r"(b[1]));
}
static __device__ __forceinline__ unsigned packbf(float a, float b) {
    __nv_bfloat162 t = __floats2bfloat162_rn(a, b);
    return *reinterpret_cast<unsigned*>(&t);
}
static __device__ __forceinline__ void cp16(uint32_t saddr, const void* gptr) {
    asm volatile("cp.async.cg.shared.global [%0], [%1], 16;" :: "r"(saddr), "l"(gptr) : "memory");
}
static __device__ __forceinline__ void cp_commit() {
    asm volatile("cp.async.commit_group;" ::: "memory");
}
static __device__ __forceinline__ void cp_wait1() {
    asm volatile("cp.async.wait_group 1;" ::: "memory");
}
static __device__ __forceinline__ void cp_wait0() {
    asm volatile("cp.async.wait_group 0;" ::: "memory");
}

#define NT 256

// ================= cvt_w: proj_w fp32 -> bf16 (once) =================
__global__ void cvt_w(const float* __restrict__ W) {
    int i = blockIdx.x * blockDim.x + threadIdx.x;  // 32768 threads x 8 elems
    const float4* p = (const float4*)(W + (size_t)i * 8);
    float4 v0 = p[0], v1 = p[1];
    uint4 u;
    u.x = packbf(v0.x, v0.y); u.y = packbf(v0.z, v0.w);
    u.z = packbf(v1.x, v1.y); u.w = packbf(v1.z, v1.w);
    *(uint4*)(g_w + (size_t)i * 8) = u;
}

// ================= proj: 64x128 tile, K=1024 in 16 chunks ============
// SMEM: stage s (s=0,1) at s*24576: A bf16 64x64 (8KB) + B bf16 128x64 (16KB)
__global__ __launch_bounds__(NT, 2) void proj_mma(const float* __restrict__ X,
                                                  const float* __restrict__ bias) {
    extern __shared__ __align__(16) char smem[];
    const uint32_t sb = smem_u32(smem);
    const int tid = threadIdx.x;
    const int warp = tid >> 5, lane = tid & 31;
    const int wm = (warp >> 2) * 32;  // 2 warps along M (64)
    const int wn = (warp & 3) * 32;   // 4 warps along N (128)
    const int mBase = blockIdx.y * 64;
    const int nBase = blockIdx.x * 128;

    // A prefetch regs: 2 chunks (row = c>>3, ch = c&7), 8 fp32 each
    float4 rA[4];
    auto ldgA = [&](int kt) {
#pragma unroll
        for (int i = 0; i < 2; i++) {
            int c = tid + i * NT;
            int row = c >> 3, ch = c & 7;
            const float4* p = (const float4*)(X + (size_t)(mBase + row) * 1024 + kt * 64 + ch * 8);
            rA[2 * i] = p[0];
            rA[2 * i + 1] = p[1];
        }
    };
    auto stsA = [&](int buf) {
        char* s = smem + buf * 24576;
#pragma unroll
        for (int i = 0; i < 2; i++) {
            int c = tid + i * NT;
            int row = c >> 3, ch = c & 7;
            uint4 u;
            u.x = packbf(rA[2 * i].x, rA[2 * i].y);
            u.y = packbf(rA[2 * i].z, rA[2 * i].w);
            u.z = packbf(rA[2 * i + 1].x, rA[2 * i + 1].y);
            u.w = packbf(rA[2 * i + 1].z, rA[2 * i + 1].w);
            *(uint4*)(s + row * 128 + ((ch ^ (row & 7)) << 4)) = u;
        }
    };
    auto issueB = [&](int kt, int buf) {
        const uint32_t B0 = sb + buf * 24576 + 8192;
#pragma unroll
        for (int i = 0; i < 4; i++) {
            int c = tid + i * NT;  // 1024 chunks: 128 rows x 8
            int row = c >> 3, ch = c & 7;
            cp16(B0 + row * 128 + ((ch ^ (row & 7)) << 4),
                 g_w + (size_t)(nBase + row) * 1024 + kt * 64 + ch * 8);
        }
        cp_commit();
    };

    float acc[2][4][4];
#pragma unroll
    for (int mi = 0; mi < 2; mi++)
#pragma unroll
        for (int ni = 0; ni < 4; ni++)
#pragma unroll
            for (int j = 0; j < 4; j++) acc[mi][ni][j] = 0.f;

    ldgA(0);
    stsA(0);
    issueB(0, 0);
    ldgA(1);

    for (int kt = 0; kt < 16; kt++) {
        cp_wait0();
        __syncthreads();  // buf kt ready; all warps past mma(kt-1)
        if (kt + 1 < 16) issueB(kt + 1, (kt + 1) & 1);
        const uint32_t aB = sb + (kt & 1) * 24576, bB = aB + 8192;
#pragma unroll
        for (int ks = 0; ks < 4; ks++) {
            unsigned af[2][4], bfr[4][2];
#pragma unroll
            for (int mi = 0; mi < 2; mi++) {
                int row = wm + mi * 16 + (lane & 15);
                int kch = ks * 2 + (lane >> 4);
                ldsm_x4(af[mi], aB + row * 128 + ((kch ^ (row & 7)) << 4));
            }
#pragma unroll
            for (int h = 0; h < 2; h++) {
                unsigned q[4];
                int nr = wn + h * 16 + (lane & 7) + ((lane >> 4) << 3);
                int kch = ks * 2 + ((lane >> 3) & 1);
                ldsm_x4(q, bB + nr * 128 + ((kch ^ (nr & 7)) << 4));
                bfr[2 * h][0] = q[0]; bfr[2 * h][1] = q[1];
                bfr[2 * h + 1][0] = q[2]; bfr[2 * h + 1][1] = q[3];
            }
#pragma unroll
            for (int mi = 0; mi < 2; mi++)
#pragma unroll
                for (int ni = 0; ni < 4; ni++) mma16816(acc[mi][ni], af[mi], bfr[ni]);
        }
        if (kt + 1 < 16) {
            stsA((kt + 1) & 1);      // safe: all warps past mma(kt-1) via this kt's sync
            if (kt + 2 < 16) ldgA(kt + 2);
        }
    }

    // epilogue: bias + relu -> g_h bf16
#pragma unroll
    for (int mi = 0; mi < 2; mi++) {
        int r = mBase + wm + mi * 16 + (lane >> 2);
#pragma unroll
        for (int ni = 0; ni < 4; ni++) {
            int cidx = nBase + wn + ni * 8 + ((lane & 3) << 1);
            float b0 = bias[cidx], b1 = bias[cidx + 1];
            float v00 = fmaxf(acc[mi][ni][0] + b0, 0.f);
            float v01 = fmaxf(acc[mi][ni][1] + b1, 0.f);
            float v10 = fmaxf(acc[mi][ni][2] + b0, 0.f);
            float v11 = fmaxf(acc[mi][ni][3] + b1, 0.f);
            *(__nv_bfloat162*)&g_h[(size_t)r * 256 + cidx] = __floats2bfloat162_rn(v00, v01);
            *(__nv_bfloat162*)&g_h[(size_t)(r + 8) * 256 + cidx] = __floats2bfloat162_rn(v10, v11);
        }
    }
}

// ================= gram: triangle tiles, 3-stage pipeline ============
// SMEM: stage s (0..2) at s*32768: A 128x64 (16KB) + B 128x64 (16KB).
// Mirror staging ct 128x132 fp32 (67584B) reuses pipeline smem.
__global__ __launch_bounds__(NT, 2) void gram_mma(const float* __restrict__ clfw,
                                                  const float* __restrict__ clfb,
                                                  float* __restrict__ out) {
    extern __shared__ __align__(16) char smem[];
    const uint32_t sb = smem_u32(smem);
    const int tid = threadIdx.x;
    const int warp = tid >> 5, lane = tid & 31;
    const int wm = (warp >> 2) * 64;
    const int wn = (warp & 3) * 32;
    const int b = blockIdx.y;

    int t = blockIdx.x, ti = 0;
    while (t >= 16 - ti) { t -= 16 - ti; ti++; }
    const int tj = ti + t;
    const int mBase = ti * 128, nBase = tj * 128;
    const __nv_bfloat16* hb = g_h + (size_t)b * (2048 * 256);

    auto issue = [&](int kt, int buf) {
        const uint32_t A0 = sb + buf * 32768, B0 = A0 + 16384;
#pragma unroll
        for (int i = 0; i < 4; i++) {
            int c = tid + i * NT;
            int r = c >> 3, ch = c & 7;
            uint32_t dst = (uint32_t)(r * 128 + ((ch ^ (r & 7)) << 4));
            cp16(A0 + dst, hb + (size_t)(mBase + r) * 256 + kt * 64 + ch * 8);
            cp16(B0 + dst, hb + (size_t)(nBase + r) * 256 + kt * 64 + ch * 8);
        }
        cp_commit();
    };

    float acc[4][4][4];
#pragma unroll
    for (int mi = 0; mi < 4; mi++)
#pragma unroll
        for (int ni = 0; ni < 4; ni++)
#pragma unroll
            for (int j = 0; j < 4; j++) acc[mi][ni][j] = 0.f;

    issue(0, 0);
    issue(1, 1);

    for (int kt = 0; kt < 4; kt++) {
        if (kt < 3) cp_wait1(); else cp_wait0();
        __syncthreads();  // chunk kt arrived; all warps past mma(kt-1)
        if (kt + 2 < 4) issue(kt + 2, (kt + 2) % 3);  // overwrites buf consumed at kt-1
        const uint32_t aB = sb + (kt % 3) * 32768, bB = aB + 16384;
#pragma unroll
        for (int ks = 0; ks < 4; ks++) {
            unsigned af[4][4], bfr[4][2];
#pragma unroll
            for (int mi = 0; mi < 4; mi++) {
                int row = wm + mi * 16 + (lane & 15);
                int kch = ks * 2 + (lane >> 4);
                ldsm_x4(af[mi], aB + row * 128 + ((kch ^ (row & 7)) << 4));
            }
#pragma unroll
            for (int h = 0; h < 2; h++) {
                unsigned q[4];
                int nr = wn + h * 16 + (lane & 7) + ((lane >> 4) << 3);
                int kch = ks * 2 + ((lane >> 3) & 1);
                ldsm_x4(q, bB + nr * 128 + ((kch ^ (nr & 7)) << 4));
                bfr[2 * h][0] = q[0]; bfr[2 * h][1] = q[1];
                bfr[2 * h + 1][0] = q[2]; bfr[2 * h + 1][1] = q[3];
            }
#pragma unroll
            for (int mi = 0; mi < 4; mi++)
#pragma unroll
                for (int ni = 0; ni < 4; ni++) mma16816(acc[mi][ni], af[mi], bfr[ni]);
        }
    }
    __syncthreads();  // all warps done reading smem before ct staging reuses it

    const float w = clfw[0], cb = clfb[0];
    float* op = out + (size_t)b * 2048 * 2048;
    float* ct = (float*)smem;  // 128 x 132 transposed staging

#pragma unroll
    for (int mi = 0; mi < 4; mi++) {
        int lr = wm + mi * 16 + (lane >> 2);
#pragma unroll
        for (int ni = 0; ni < 4; ni++) {
            int lc = wn + ni * 8 + ((lane & 3) << 1);
            float v00 = fmaf(acc[mi][ni][0], w, cb);
            float v01 = fmaf(acc[mi][ni][1], w, cb);
            float v10 = fmaf(acc[mi][ni][2], w, cb);
            float v11 = fmaf(acc[mi][ni][3], w, cb);
            *(float2*)&op[(size_t)(mBase + lr) * 2048 + nBase + lc] = make_float2(v00, v01);
            *(float2*)&op[(size_t)(mBase + lr + 8) * 2048 + nBase + lc] = make_float2(v10, v11);
            if (ti != tj) {
                ct[lc * 132 + lr] = v00;
                ct[(lc + 1) * 132 + lr] = v01;
                ct[lc * 132 + lr + 8] = v10;
                ct[(lc + 1) * 132 + lr + 8] = v11;
            }
        }
    }
    if (ti != tj) {
        __syncthreads();
#pragma unroll
        for (int idx = tid; idx < 4096; idx += NT) {
            int rr = idx >> 5, cc = idx & 31;
            float4 v = *(float4*)&ct[rr * 132 + cc * 4];
            *(float4*)&op[(size_t)(nBase + rr) * 2048 + mBase + cc * 4] = v;
        }
    }
}

extern "C" void kernel_launch(void* const* d_in, const int* in_sizes, int n_in,
                              void* d_out, int out_size) {
    (void)in_sizes; (void)n_in; (void)out_size;
    const float* hidden = (const float*)d_in[0];  // [4,2048,1024]
    const float* proj_w = (const float*)d_in[1];  // [256,1024]
    const float* proj_b = (const float*)d_in[2];  // [256]
    const float* clf_w = (const float*)d_in[3];   // [1,1]
    const float* clf_b = (const float*)d_in[4];   // [1]
    float* out = (float*)d_out;                   // [4,2048,2048]

    cudaFuncSetAttribute(proj_mma, cudaFuncAttributeMaxDynamicSharedMemorySize, 49152);
    cudaFuncSetAttribute(gram_mma, cudaFuncAttributeMaxDynamicSharedMemorySize, 98304);

    cvt_w<<<128, NT>>>(proj_w);
    // proj: [8192,1024] x [256,1024]^T -> relu -> g_h ; 2 N-tiles x 128 M-tiles
    proj_mma<<<dim3(2, 128), NT, 49152>>>(hidden, proj_b);
    // gram: 136 triangle tiles x 4 batches
    gram_mma<<<dim3(136, 4), NT, 98304>>>(clf_w, clf_b, out);
}